// round 14
// baseline (speedup 1.0000x reference)
#include <cuda_runtime.h>
#include <cuda_fp16.h>
#include <cuda_bf16.h>
#include <cstdint>

// Problem constants (fixed by the reference)
#define IN_N  (512 * 512)   // input pixels per batch
#define NB    64            // batch
#define NO    (512 * 512)   // outputs
#define NK    8             // connections per output

#define GRID_T   1036       // persistent transpose grid (7 CTAs/SM x 148)
#define NTILES   (IN_N / 64)

// Scratch: input transposed to (N, B) in fp16: each index row is a contiguous
// 128B run of all 64 batch values (33.5 MB, L2-resident).
__device__ __align__(256) __half g_xTh[(size_t)IN_N * NB];

static __device__ __forceinline__ unsigned int smem_u32(const void* p) {
    return (unsigned int)__cvta_generic_to_shared(p);
}

// ---------------------------------------------------------------------------
// Kernel 1: transpose (B, N) f32 -> (N, B) f16 — cp.async pipelined version.
//
// R11 showed register-staged loads cap in-flight bytes (RF-conserved); this
// version stages through smem via LDGSTS so latency is hidden by pipeline
// depth, not registers.
//
// Tile = 64 n x 64 b (16 KB fp32), double-buffered (32 KB smem).
// smem layout: 8B chunk (b, cx) [fp32 pair n=2cx,2cx+1] stored at word
//   b*64 + ((cx ^ (b&31)) << 1)
// Load:  warp-per-row-group: b = warp + 8i, cx = lane -> 256B contiguous
//        global src per warp; cp.async.ca 8B.
// Convert: unit (nl, g): 8 fp32 column reads b=8g..8g+7. Lane decomposition
//   nl = (warp&3)*16 + (lane&15), gp = lane>>4, g = gp + 2m makes every LDS
//   instruction hit 32 distinct banks (g parity enters bank bit4 via the
//   b&31 XOR key; (w, cx&7) covers the 16 banks within each half).
// Stores: pairs of adjacent 16B -> 32B-sector-aligned STG (sector-exact).
// Output values/layout bit-identical to R12's transpose.
// ---------------------------------------------------------------------------
__global__ void __launch_bounds__(256) transpose_kernel(const float* __restrict__ in) {
    __shared__ __align__(16) float buf[2][64 * 64];   // 2 x 16 KB
    const int t    = threadIdx.x;
    const int warp = t >> 5;
    const int lane = t & 31;

    uint4* __restrict__ xT4 = reinterpret_cast<uint4*>(g_xTh);

    // ---- tile loader: 8 cp.async 8B per thread + one commit ----
    auto load_tile = [&](int tile, int pb) {
        const int n0 = tile * 64;
        const unsigned int sbase = smem_u32(&buf[pb][0]);
#pragma unroll
        for (int i = 0; i < 8; i++) {
            const int b  = warp + 8 * i;            // row 0..63 (const per warp)
            const int cx = lane;                    // 8B chunk 0..31
            const unsigned int dst =
                sbase + (unsigned int)((b * 64 + ((cx ^ (b & 31)) << 1)) * 4);
            const float* src = in + (size_t)b * IN_N + n0 + cx * 2;
            asm volatile("cp.async.ca.shared.global [%0], [%1], 8;"
                         :: "r"(dst), "l"(src));
        }
        asm volatile("cp.async.commit_group;");
    };

    // ---- conversion phase for one tile ----
    auto process_tile = [&](int tile, int pb) {
        const int n0 = tile * 64;
        const float* fb = &buf[pb][0];
        const int nl    = (warp & 3) * 16 + (lane & 15);  // 0..63
        const int gp    = lane >> 4;                      // g parity
        const int mbase = (warp >> 2) * 2;                // warps 0-3: m=0,1; 4-7: m=2,3
        const int cx    = nl >> 1;
        const int w     = nl & 1;
#pragma unroll
        for (int mm = 0; mm < 2; mm++) {
            const int g = gp + 2 * (mbase + mm);          // 0..7, g&1 == gp
            float fv[8];
#pragma unroll
            for (int i = 0; i < 8; i++) {
                const int b = 8 * g + i;
                fv[i] = fb[b * 64 + ((cx ^ (b & 31)) << 1) + w];
            }
            __half2 h0 = __floats2half2_rn(fv[0], fv[1]);
            __half2 h1 = __floats2half2_rn(fv[2], fv[3]);
            __half2 h2 = __floats2half2_rn(fv[4], fv[5]);
            __half2 h3 = __floats2half2_rn(fv[6], fv[7]);
            uint4 o;
            o.x = *reinterpret_cast<unsigned int*>(&h0);
            o.y = *reinterpret_cast<unsigned int*>(&h1);
            o.z = *reinterpret_cast<unsigned int*>(&h2);
            o.w = *reinterpret_cast<unsigned int*>(&h3);
            xT4[(size_t)(n0 + nl) * 8 + g] = o;           // 32B-sector pairs
        }
    };

    // ---- persistent double-buffered pipeline ----
    int tile = blockIdx.x;
    if (tile < NTILES) load_tile(tile, 0);
    int p = 0;
    for (; tile < NTILES; tile += GRID_T) {
        const int next = tile + GRID_T;
        if (next < NTILES) {
            load_tile(next, p ^ 1);
            asm volatile("cp.async.wait_group 1;");
        } else {
            asm volatile("cp.async.wait_group 0;");
        }
        __syncthreads();
        process_tile(tile, p);
        __syncthreads();    // protect buf[p] before it is reloaded next iter
        p ^= 1;
    }
}

// ---------------------------------------------------------------------------
// Kernel 2: gather + weighted reduce with packed HFMA2 accumulation.
// (EXACT R7/R12 kernel — ~94% of the LTS byte cap, compulsory-only DRAM.)
// ---------------------------------------------------------------------------
__global__ void __launch_bounds__(256) sparse_linear_kernel(
    const int*   __restrict__ conn,
    const float* __restrict__ w,
    float*       __restrict__ out)
{
    __shared__ float so[64][33];     // [batch][o_local], pitch 33

    const int warp   = threadIdx.x >> 5;
    const int lane   = threadIdx.x & 31;
    const int o_base = blockIdx.x * 32;
    const int o_warp = o_base + warp * 4;
    const int j      = lane >> 3;    // output within warp's 4
    const int c      = lane & 7;     // batch chunk (8 batches)

    // Coalesced: warp's 4 conn/weight rows (4 x 8 = 32 elems)
    const int   ci  = conn[(size_t)o_warp * NK + lane];
    const float wf  = w   [(size_t)o_warp * NK + lane];
    const int   wib = (int)__half_as_ushort(__float2half_rn(wf));

    const uint4* __restrict__ xT4 = reinterpret_cast<const uint4*>(g_xTh);

    __half2 accE[4], accO[4];        // even-k / odd-k chains (depth 4 each)
#pragma unroll
    for (int m = 0; m < 4; m++) {
        accE[m] = __half2half2(__ushort_as_half((unsigned short)0));
        accO[m] = accE[m];
    }

#pragma unroll
    for (int k = 0; k < NK; k++) {
        int src   = (lane & 24) + k;                    // lane j*8 + k
        int   idx = __shfl_sync(0xffffffffu, ci,  src);
        int   wb  = __shfl_sync(0xffffffffu, wib, src);
        __half2 wk2 = __half2half2(__ushort_as_half((unsigned short)wb));
        uint4 v = xT4[(size_t)idx * 8 + c];             // 512B/warp: 4 rows
        __half2* acc = (k & 1) ? accO : accE;
        acc[0] = __hfma2(wk2, *reinterpret_cast<__half2*>(&v.x), acc[0]);
        acc[1] = __hfma2(wk2, *reinterpret_cast<__half2*>(&v.y), acc[1]);
        acc[2] = __hfma2(wk2, *reinterpret_cast<__half2*>(&v.z), acc[2]);
        acc[3] = __hfma2(wk2, *reinterpret_cast<__half2*>(&v.w), acc[3]);
    }

    // Epilogue: merge chains in fp32, stage to smem.
#pragma unroll
    for (int m = 0; m < 4; m++) {
        float2 e = __half22float2(accE[m]);
        float2 o = __half22float2(accO[m]);
        so[c * 8 + 2 * m    ][warp * 4 + j] = e.x + o.x;
        so[c * 8 + 2 * m + 1][warp * 4 + j] = e.y + o.y;
    }
    __syncthreads();

    // Coalesced write-out: lane oc -> output column, 8 batch rows per thread
    const int oc = threadIdx.x & 31;
    const int br = threadIdx.x >> 5;
#pragma unroll
    for (int i = 0; i < 8; i++) {
        int b = br * 8 + i;
        out[(size_t)b * NO + o_base + oc] = so[b][oc];  // conflict-free LDS
    }
}

extern "C" void kernel_launch(void* const* d_in, const int* in_sizes, int n_in,
                              void* d_out, int out_size) {
    const float* input = (const float*)d_in[0];   // (64, 512, 512) f32
    const int*   conn  = (const int*)  d_in[1];   // (O, 8) i32
    const float* wts   = (const float*)d_in[2];   // (O, 8) f32
    float*       out   = (float*)d_out;           // (64, O) f32

    transpose_kernel<<<GRID_T, 256>>>(input);
    sparse_linear_kernel<<<NO / 32, 256>>>(conn, wts, out);
}

// round 15
// speedup vs baseline: 1.1661x; 1.1661x over previous
#include <cuda_runtime.h>
#include <cuda_fp16.h>
#include <cuda_bf16.h>
#include <cstdint>

// Problem constants (fixed by the reference)
#define IN_N  (512 * 512)   // input pixels per batch
#define NB    64            // batch
#define NO    (512 * 512)   // outputs
#define NK    8             // connections per output

// Scratch: input transposed to (N, B) in fp16: each index row is a contiguous
// 128B run of all 64 batch values (33.5 MB, L2-resident).
__device__ __align__(256) __half g_xTh[(size_t)IN_N * NB];

static __device__ __forceinline__ unsigned int h2bits(__half2 h) {
    return *reinterpret_cast<unsigned int*>(&h);
}

// ---------------------------------------------------------------------------
// Kernel 1: transpose (B, N) f32 -> (N, B) f16.
// R12's 128n x 64b tile version with ONE change: input loads use __ldcs
// (evict-first). Theory: default-policy input streaming evicts the dirty
// xTh lines from L2, adding ~33.5 MB of DRAM writebacks (100 MB total ->
// 17us). Streaming loads keep xTh resident; DRAM traffic drops to the
// 67 MB compulsory read.
// ---------------------------------------------------------------------------
__global__ void __launch_bounds__(256) transpose_kernel(const float* __restrict__ in) {
    __shared__ __align__(16) unsigned int s[128 * 32];   // 16 KB
    const int n0 = blockIdx.x * 128;
    const int t  = threadIdx.x;

    // ---- Phase 1: 8 front-batched streaming float4 loads, convert + STS ----
    const int q0 = t & 15;        // base n-quad
    const int b0 = t >> 4;        // base batch-pair (0..15)

    float4 A[2][2], B[2][2];      // [i: bh half][j: q half]
#pragma unroll
    for (int i = 0; i < 2; i++) {
        const int bh = b0 + 16 * i;               // 0..31
        const float4* __restrict__ r0 =
            reinterpret_cast<const float4*>(in + (size_t)(2 * bh) * IN_N);
        const float4* __restrict__ r1 =
            reinterpret_cast<const float4*>(in + (size_t)(2 * bh + 1) * IN_N);
#pragma unroll
        for (int jq = 0; jq < 2; jq++) {
            const int q = q0 + 16 * jq;           // 0..31
            A[i][jq] = __ldcs(&r0[(n0 >> 2) + q]);   // evict-first streaming
            B[i][jq] = __ldcs(&r1[(n0 >> 2) + q]);
        }
    }

#pragma unroll
    for (int i = 0; i < 2; i++) {
        const int bh    = b0 + 16 * i;
        const int chunk = bh >> 2;                // 0..7
        const int r2    = bh & 3;
#pragma unroll
        for (int jq = 0; jq < 2; jq++) {
            const int q = q0 + 16 * jq;           // row>>2 == q
            float av[4] = {A[i][jq].x, A[i][jq].y, A[i][jq].z, A[i][jq].w};
            float bv[4] = {B[i][jq].x, B[i][jq].y, B[i][jq].z, B[i][jq].w};
            const int sw = chunk ^ (q & 7);
#pragma unroll
            for (int e = 0; e < 4; e++) {
                int row = 4 * q + e;              // 0..127
                s[row * 32 + sw * 4 + r2] =
                    h2bits(__floats2half2_rn(av[e], bv[e]));
            }
        }
    }
    __syncthreads();

    // ---- Phase 2: LDS.128 + contiguous STG.128 ----
    uint4* __restrict__ xT4 = reinterpret_cast<uint4*>(g_xTh);
#pragma unroll
    for (int i1 = 0; i1 < 4; i1++) {
        int u  = t + 256 * i1;                    // 0..1023
        int nl = u >> 3;                          // 0..127
        int g  = u & 7;                           // 16B chunk of 128B row
        int sw = g ^ ((nl >> 2) & 7);
        uint4 v = *reinterpret_cast<const uint4*>(&s[nl * 32 + sw * 4]);
        xT4[(size_t)(n0 + nl) * 8 + g] = v;       // 512B/warp contiguous
    }
}

// ---------------------------------------------------------------------------
// Kernel 2: gather + weighted reduce with packed HFMA2 accumulation.
// (EXACT R7/R12 kernel — ~94% of the LTS byte cap, compulsory-only DRAM.)
// ---------------------------------------------------------------------------
__global__ void __launch_bounds__(256) sparse_linear_kernel(
    const int*   __restrict__ conn,
    const float* __restrict__ w,
    float*       __restrict__ out)
{
    __shared__ float so[64][33];     // [batch][o_local], pitch 33

    const int warp   = threadIdx.x >> 5;
    const int lane   = threadIdx.x & 31;
    const int o_base = blockIdx.x * 32;
    const int o_warp = o_base + warp * 4;
    const int j      = lane >> 3;    // output within warp's 4
    const int c      = lane & 7;     // batch chunk (8 batches)

    // Coalesced: warp's 4 conn/weight rows (4 x 8 = 32 elems)
    const int   ci  = conn[(size_t)o_warp * NK + lane];
    const float wf  = w   [(size_t)o_warp * NK + lane];
    const int   wib = (int)__half_as_ushort(__float2half_rn(wf));

    const uint4* __restrict__ xT4 = reinterpret_cast<const uint4*>(g_xTh);

    __half2 accE[4], accO[4];        // even-k / odd-k chains (depth 4 each)
#pragma unroll
    for (int m = 0; m < 4; m++) {
        accE[m] = __half2half2(__ushort_as_half((unsigned short)0));
        accO[m] = accE[m];
    }

#pragma unroll
    for (int k = 0; k < NK; k++) {
        int src   = (lane & 24) + k;                    // lane j*8 + k
        int   idx = __shfl_sync(0xffffffffu, ci,  src);
        int   wb  = __shfl_sync(0xffffffffu, wib, src);
        __half2 wk2 = __half2half2(__ushort_as_half((unsigned short)wb));
        uint4 v = xT4[(size_t)idx * 8 + c];             // 512B/warp: 4 rows
        __half2* acc = (k & 1) ? accO : accE;
        acc[0] = __hfma2(wk2, *reinterpret_cast<__half2*>(&v.x), acc[0]);
        acc[1] = __hfma2(wk2, *reinterpret_cast<__half2*>(&v.y), acc[1]);
        acc[2] = __hfma2(wk2, *reinterpret_cast<__half2*>(&v.z), acc[2]);
        acc[3] = __hfma2(wk2, *reinterpret_cast<__half2*>(&v.w), acc[3]);
    }

    // Epilogue: merge chains in fp32, stage to smem.
#pragma unroll
    for (int m = 0; m < 4; m++) {
        float2 e = __half22float2(accE[m]);
        float2 o = __half22float2(accO[m]);
        so[c * 8 + 2 * m    ][warp * 4 + j] = e.x + o.x;
        so[c * 8 + 2 * m + 1][warp * 4 + j] = e.y + o.y;
    }
    __syncthreads();

    // Coalesced write-out: lane oc -> output column, 8 batch rows per thread
    const int oc = threadIdx.x & 31;
    const int br = threadIdx.x >> 5;
#pragma unroll
    for (int i = 0; i < 8; i++) {
        int b = br * 8 + i;
        out[(size_t)b * NO + o_base + oc] = so[b][oc];  // conflict-free LDS
    }
}

extern "C" void kernel_launch(void* const* d_in, const int* in_sizes, int n_in,
                              void* d_out, int out_size) {
    const float* input = (const float*)d_in[0];   // (64, 512, 512) f32
    const int*   conn  = (const int*)  d_in[1];   // (O, 8) i32
    const float* wts   = (const float*)d_in[2];   // (O, 8) f32
    float*       out   = (float*)d_out;           // (64, O) f32

    transpose_kernel<<<IN_N / 128, 256>>>(input);
    sparse_linear_kernel<<<NO / 32, 256>>>(conn, wts, out);
}